// round 1
// baseline (speedup 1.0000x reference)
#include <cuda_runtime.h>
#include <math.h>

#define NB 4          // batch / classes
#define DD 512        // feature dim
#define CB 8          // compute blocks (each handles 64 output columns)
#define TPB 256
#define ALPHA_IT 0.7f
#define BETA_IT  0.5f

__global__ void __launch_bounds__(TPB)
graphlearner_fused(const float* __restrict__ bt,    // base_text_features (4,512)
                   const float* __restrict__ bi,    // base_img_features  (4,512)
                   const float* __restrict__ img,   // img_feature (40960,512)
                   const float* __restrict__ Wtt,   // (512,512)
                   const float* __restrict__ btt,   // (4,512)
                   const float* __restrict__ Wit,   // (512,512)
                   const float* __restrict__ bit_,  // (4,512)
                   float* __restrict__ out,         // refined(4,512) ++ img(40960,512)
                   long long n_img_f4)
{
    const int tid = threadIdx.x;

    // ---------------- copy blocks: stream img_feature -> out + 2048 --------
    if (blockIdx.x >= CB) {
        const float4* __restrict__ src = (const float4*)img;
        float4* __restrict__ dst = (float4*)(out + NB * DD);
        long long i      = (long long)(blockIdx.x - CB) * TPB + tid;
        long long stride = (long long)(gridDim.x - CB) * TPB;
        for (; i < n_img_f4; i += stride)
            dst[i] = src[i];
        return;
    }

    // ---------------- compute blocks ---------------------------------------
    __shared__ float bt_s[NB][DD];
    __shared__ float bi_s[NB][DD];
    __shared__ float v_tt[NB][DD];
    __shared__ float v_it[NB][DD];
    __shared__ float raw[3][NB][NB];   // 0: bt.bt  1: bt.bi  2: bi.bi
    __shared__ float c_tt[NB][5];
    __shared__ float c_it[NB][5];
    __shared__ float pacc[4][64][8];

    // load bt, bi into shared
    for (int i = tid; i < NB * DD; i += TPB) {
        ((float*)bt_s)[i] = bt[i];
        ((float*)bi_s)[i] = bi[i];
    }
    __syncthreads();

    // 48 dot products (3 gram matrices, 4x4 each), one warp per dot, 8 warps
    {
        const int warp = tid >> 5, lane = tid & 31;
        for (int q = warp; q < 48; q += 8) {
            const int mat = q >> 4, i = (q & 15) >> 2, j = q & 3;
            const float* a = (mat == 2) ? bi_s[i] : bt_s[i];
            const float* c = (mat == 0) ? bt_s[j] : bi_s[j];
            float s = 0.f;
            for (int k = lane; k < DD; k += 32) s += a[k] * c[k];
            #pragma unroll
            for (int off = 16; off > 0; off >>= 1)
                s += __shfl_down_sync(0xffffffffu, s, off);
            if (lane == 0) raw[mat][i][j] = s;
        }
    }
    __syncthreads();

    // 8 tiny graphs: threads 0..3 -> tt for b, threads 4..7 -> it for b
    if (tid < 8) {
        const int b = tid & 3;
        const bool is_it = tid >= 4;
        float nt[NB], ni[NB];
        #pragma unroll
        for (int i = 0; i < NB; i++) {
            nt[i] = fmaxf(sqrtf(raw[0][i][i]), 1e-12f);
            ni[i] = fmaxf(sqrtf(raw[2][i][i]), 1e-12f);
        }
        float e[5][5];
        if (!is_it) {
            e[0][0] = raw[0][b][b] / (nt[b] * nt[b]);
            #pragma unroll
            for (int m = 1; m < 5; m++) {
                e[0][m] = raw[0][b][m - 1] / (nt[b] * nt[m - 1]);
                e[m][0] = raw[0][m - 1][b] / (nt[m - 1] * nt[b]);
            }
            #pragma unroll
            for (int n = 1; n < 5; n++)
                #pragma unroll
                for (int m = 1; m < 5; m++)
                    e[n][m] = raw[0][n - 1][m - 1] / (nt[n - 1] * nt[m - 1]);
        } else {
            e[0][0] = raw[0][b][b] / (nt[b] * nt[b]);
            #pragma unroll
            for (int m = 1; m < 5; m++) {
                e[0][m] = raw[1][b][m - 1] / (nt[b] * ni[m - 1]);
                e[m][0] = e[0][m];
            }
            #pragma unroll
            for (int n = 1; n < 5; n++)
                #pragma unroll
                for (int m = 1; m < 5; m++)
                    e[n][m] = raw[2][n - 1][m - 1] / (ni[n - 1] * ni[m - 1]);
        }
        float adj[5][5], deg[5];
        #pragma unroll
        for (int n = 0; n < 5; n++) {
            deg[n] = 0.f;
            #pragma unroll
            for (int m = 0; m < 5; m++) {
                adj[n][m] = fmaxf(e[n][m], 0.f) + ((n == m) ? 1.f : 0.f);
                deg[n] += adj[n][m];
            }
        }
        float dinv[5];
        #pragma unroll
        for (int n = 0; n < 5; n++)
            dinv[n] = (deg[n] > 0.f) ? (1.f / sqrtf(deg[n])) : 0.f;
        float* cc = is_it ? c_it[b] : c_tt[b];
        #pragma unroll
        for (int m = 0; m < 5; m++)
            cc[m] = dinv[0] * adj[0][m] * dinv[m];
    }
    __syncthreads();

    // combined vectors v[b] = c[b,0]*node0 + sum_j c[b,j+1]*node_{j+1}
    for (int i = tid; i < NB * DD; i += TPB) {
        const int b = i / DD, k = i % DD;
        float vt = c_tt[b][0] * bt_s[b][k];
        float vi = c_it[b][0] * bt_s[b][k];
        #pragma unroll
        for (int j = 0; j < 4; j++) {
            vt += c_tt[b][j + 1] * bt_s[j][k];
            vi += c_it[b][j + 1] * bi_s[j][k];
        }
        v_tt[b][k] = vt;
        v_it[b][k] = vi;
    }
    __syncthreads();

    // dual GEMV: 4 k-splits x 64 columns per block
    const int col = tid & 63;
    const int ksp = tid >> 6;
    const int d   = blockIdx.x * 64 + col;
    float att[NB] = {0.f, 0.f, 0.f, 0.f};
    float ait[NB] = {0.f, 0.f, 0.f, 0.f};
    const int k0 = ksp * 128;
    #pragma unroll 4
    for (int kk = 0; kk < 128; kk++) {
        const int k = k0 + kk;
        const float wt = Wtt[k * DD + d];
        const float wi = Wit[k * DD + d];
        #pragma unroll
        for (int b = 0; b < NB; b++) {
            att[b] += v_tt[b][k] * wt;
            ait[b] += v_it[b][k] * wi;
        }
    }
    #pragma unroll
    for (int b = 0; b < NB; b++) {
        pacc[ksp][col][b]     = att[b];
        pacc[ksp][col][4 + b] = ait[b];
    }
    __syncthreads();

    if (ksp == 0) {
        #pragma unroll
        for (int b = 0; b < NB; b++) {
            float stt = pacc[0][col][b] + pacc[1][col][b] +
                        pacc[2][col][b] + pacc[3][col][b] + btt[b * DD + d];
            float sit = pacc[0][col][4 + b] + pacc[1][col][4 + b] +
                        pacc[2][col][4 + b] + pacc[3][col][4 + b] + bit_[b * DD + d];
            float g = ALPHA_IT * tanhf(stt) + (1.f - ALPHA_IT) * tanhf(sit);
            out[b * DD + d] = BETA_IT * bt_s[b][d] + (1.f - BETA_IT) * g;
        }
    }
}

extern "C" void kernel_launch(void* const* d_in, const int* in_sizes, int n_in,
                              void* d_out, int out_size) {
    const float* bt   = (const float*)d_in[0];
    const float* bi   = (const float*)d_in[1];
    const float* img  = (const float*)d_in[2];
    const float* Wtt  = (const float*)d_in[3];
    const float* btt  = (const float*)d_in[4];
    const float* Wit  = (const float*)d_in[5];
    const float* bit_ = (const float*)d_in[6];
    float* out = (float*)d_out;

    const long long n_img   = (long long)in_sizes[2];   // 40960*512
    const long long n_img_f4 = n_img / 4;

    const int copy_blocks = 148 * 8;                    // saturate HBM
    dim3 grid(CB + copy_blocks), block(TPB);
    graphlearner_fused<<<grid, block>>>(bt, bi, img, Wtt, btt, Wit, bit_,
                                        out, n_img_f4);
}